// round 10
// baseline (speedup 1.0000x reference)
#include <cuda_runtime.h>

// LFQ quantizer, factorized-softmax formulation, v7.
// v6 -> v7: reduce kernel gets its MLP from occupancy, not per-thread regs:
//   128 blocks x 1024 threads, 32 chunks x <=3 rgs/thread, 3 float4 in regs.
//
// probs_j = prod_d sigmoid(400*s_d(j)*x_d) = f(lo 8 bits) * g(hi 6 bits).
// avg_probs = (1/4096) F^T G computed as split-K rank-1 accumulation.

#define RG      74          // row groups
#define RPB     56          // rows per group (last group has 8 valid)
#define GRID_A  (RG * 4)    // 296 blocks = 2 x 148 SMs
#define NT_A    512
#define NCODES  16384
#define NROW    4096
#define NDIM    14
#define NBLK_B  128
#define NT_B    1024

// scratch (__device__ globals; no allocations allowed)
__device__ float g_partial[RG * NCODES];           // 4.85 MB split-K partials
__device__ float g_pH[RG];
__device__ float g_pC[RG];
__device__ unsigned long long g_accT;              // fixed-point sum of a*log(a+eps)
__device__ unsigned int g_ticket;

#define FIX_SCALE 1099511627776.0   // 2^40

// dynamic smem layout (floats)
#define OF_F    0                     // f  [RPB][256]
#define OF_SG   (RPB * 256)           // sg [RPB][64]
#define OF_SQ   (OF_SG + RPB * 64)    // sq [RPB][NDIM][2]
#define OF_F03  (OF_SQ + RPB * NDIM * 2)  // f03 [RPB][16]
#define OF_F47  (OF_F03 + RPB * 16)       // f47 [RPB][16]
#define OF_WH   (OF_F47 + RPB * 16)       // swH [16]
#define OF_WC   (OF_WH + 16)              // swC [16]
#define SMEM_FLOATS (OF_WC + 16)
#define SMEM_BYTES  (SMEM_FLOATS * 4)

__global__ __launch_bounds__(NT_A, 2) void lfq_rows_kernel(const float* __restrict__ x,
                                                           float* __restrict__ out)
{
    extern __shared__ __align__(16) float sm[];
    float* F   = sm + OF_F;     // [RPB][256]
    float* SG  = sm + OF_SG;    // [RPB][64]
    float* SQ  = sm + OF_SQ;    // [RPB][NDIM][2]
    float* F03 = sm + OF_F03;   // [RPB][16]
    float* F47 = sm + OF_F47;
    float* SWH = sm + OF_WH;
    float* SWC = sm + OF_WC;

    const int t  = threadIdx.x;
    const int b  = blockIdx.x;
    const int rg = b >> 2;          // row group
    const int h  = b & 3;           // hi quarter
    const int row0  = rg * RPB;
    const int valid = min(RPB, NROW - row0);

    // reset cross-kernel accumulators (visible to kernel B via launch boundary)
    if (b == 0 && t == 0) { g_accT = 0ull; g_ticket = 0u; }

    // ---- phase 0: per-element Bernoulli tables; h==0 also emits outputs/H/C ----
    float hS = 0.f, cS = 0.f;
#pragma unroll
    for (int k = 0; k < 2; k++) {
        const int e = t + NT_A * k;             // covers RPB*NDIM = 784
        if (e < RPB * NDIM) {
            const int row = e / NDIM;
            if (row < valid) {
                const int d = e - row * NDIM;
                const float xv = x[(row0 + row) * NDIM + d];
                const int pos = xv > 0.f ? 1 : 0;
                const float au = fabsf(400.f * xv);
                const float ee = __expf(-au);                  // e^{-|u|}
                const float qmaj = __fdividef(1.f, 1.f + ee);  // sigmoid(|u|)
                const float qmin = ee * qmaj;                  // sigmoid(-|u|)
                SQ[(row * NDIM + d) * 2 + pos]     = qmaj;
                SQ[(row * NDIM + d) * 2 + 1 - pos] = qmin;
                if (h == 0) {
                    hS += log1pf(ee) + qmin * au;              // binary entropy (nats)
                    const float cm = fabsf(xv) - 1.f;
                    cS += cm * cm;
                    out[(row0 + row) * NDIM + d] = pos ? 1.f : -1.f;
                }
            } else {
                const int d = e - row * NDIM;
                SQ[(row * NDIM + d) * 2 + 0] = 0.f;
                SQ[(row * NDIM + d) * 2 + 1] = 0.f;
            }
        }
    }
    if (h == 0) {
        // big-endian packed index, one thread per row
        if (t < valid) {
            int idx = 0;
#pragma unroll
            for (int d = 0; d < NDIM; d++)
                idx |= (x[(row0 + t) * NDIM + d] > 0.f) ? (1 << (13 - d)) : 0;
            out[NROW * NDIM + row0 + t] = (float)idx;
        }
        // warp-level H/C reduce
#pragma unroll
        for (int off = 16; off > 0; off >>= 1) {
            hS += __shfl_down_sync(0xFFFFFFFFu, hS, off);
            cS += __shfl_down_sync(0xFFFFFFFFu, cS, off);
        }
        if ((t & 31) == 0) { SWH[t >> 5] = hS; SWC[t >> 5] = cS; }
    }
    __syncthreads();

    // ---- phase A1: f03 / f47 sub-products ----
#pragma unroll
    for (int k = 0; k < 4; k++) {
        const int e = t + NT_A * k;             // covers [0, 2048) >= 2*RPB*16 = 1792
        if (e < RPB * 16) {
            const int row = e >> 4, i = e & 15;
            const float* q = SQ + row * NDIM * 2;
            F03[e] = q[0 * 2 + (i & 1)] * q[1 * 2 + ((i >> 1) & 1)] *
                     q[2 * 2 + ((i >> 2) & 1)] * q[3 * 2 + ((i >> 3) & 1)];
        } else if (e < 2 * RPB * 16) {
            const int e2 = e - RPB * 16;
            const int row = e2 >> 4, i = e2 & 15;
            const float* q = SQ + row * NDIM * 2;
            F47[e2] = q[4 * 2 + (i & 1)] * q[5 * 2 + ((i >> 1) & 1)] *
                      q[6 * 2 + ((i >> 2) & 1)] * q[7 * 2 + ((i >> 3) & 1)];
        }
    }
    __syncthreads();

    // ---- phase A2: full f table + g table (exact coverage, no guards) ----
#pragma unroll
    for (int k = 0; k < 28; k++) {
        const int e = t + NT_A * k;             // RPB*256 = 14336 = 28*512
        const int row = e >> 8, lo = e & 255;
        F[e] = F03[row * 16 + (lo & 15)] * F47[row * 16 + (lo >> 4)];
    }
#pragma unroll
    for (int k = 0; k < 7; k++) {
        const int e = t + NT_A * k;             // RPB*64 = 3584 = 7*512
        const int row = e >> 6, hc = e & 63;
        const float* q = SQ + row * NDIM * 2;
        SG[e] = q[8 * 2 + (hc & 1)] * q[9 * 2 + ((hc >> 1) & 1)] *
                q[10 * 2 + ((hc >> 2) & 1)] * q[11 * 2 + ((hc >> 3) & 1)] *
                q[12 * 2 + ((hc >> 4) & 1)] * q[13 * 2 + ((hc >> 5) & 1)];
    }
    __syncthreads();

    // ---- phase B: barrier-free rank-1 accumulation (FMA-bound) ----
    const int p   = t & 127;                    // lo pair: lo = 2p, 2p+1
    const int sub = t >> 7;                     // 0..3
    const int hi0 = h * 16 + sub * 4;           // this thread's 4 hi values

    float2 acc[4];
#pragma unroll
    for (int k = 0; k < 4; k++) acc[k] = make_float2(0.f, 0.f);

#pragma unroll 4
    for (int r = 0; r < valid; r++) {
        const float2 fp = *reinterpret_cast<const float2*>(F + r * 256 + 2 * p);  // LDS.64
        const float4 gv = *reinterpret_cast<const float4*>(SG + r * 64 + hi0);    // LDS.128 bcast
        acc[0].x = fmaf(fp.x, gv.x, acc[0].x);  acc[0].y = fmaf(fp.y, gv.x, acc[0].y);
        acc[1].x = fmaf(fp.x, gv.y, acc[1].x);  acc[1].y = fmaf(fp.y, gv.y, acc[1].y);
        acc[2].x = fmaf(fp.x, gv.z, acc[2].x);  acc[2].y = fmaf(fp.y, gv.z, acc[2].y);
        acc[3].x = fmaf(fp.x, gv.w, acc[3].x);  acc[3].y = fmaf(fp.y, gv.w, acc[3].y);
    }

    // store partials: code j = hi*256 + lo
    float2* gp = reinterpret_cast<float2*>(g_partial + rg * NCODES);
#pragma unroll
    for (int k = 0; k < 4; k++)
        gp[((hi0 + k) * 256 + 2 * p) >> 1] = acc[k];

    if (h == 0 && t == 0) {
        float H = 0.f, C = 0.f;
#pragma unroll
        for (int w = 0; w < 16; w++) { H += SWH[w]; C += SWC[w]; }
        g_pH[rg] = H; g_pC[rg] = C;
    }
}

// Reduce: 128 blocks x 1024 threads. Thread = (quad, chunk).
//   quad  = blockIdx.x*32 + (t & 31)   -> 4 consecutive codes (float4)
//   chunk = t >> 5  (0..31)            -> rgs {chunk*3 + k, k<3} ∩ [0,74)
// 32 warps/SM of 3-deep float4 loads => ~4.5 MB in flight chip-wide.
__global__ __launch_bounds__(NT_B, 1) void lfq_reduce_kernel(float* __restrict__ out)
{
    const int t = threadIdx.x;
    const int quad  = blockIdx.x * 32 + (t & 31);
    const int chunk = t >> 5;
    const int rg0 = chunk * 3;

    const float4* gp = reinterpret_cast<const float4*>(g_partial) + quad;

    float4 v[3];
#pragma unroll
    for (int k = 0; k < 3; k++) {
        v[k] = make_float4(0.f, 0.f, 0.f, 0.f);
        if (rg0 + k < RG)
            v[k] = gp[(rg0 + k) * (NCODES / 4)];   // LDG.128, 512B/warp coalesced
    }

    float4 s;
    s.x = (v[0].x + v[1].x) + v[2].x;
    s.y = (v[0].y + v[1].y) + v[2].y;
    s.z = (v[0].z + v[1].z) + v[2].z;
    s.w = (v[0].w + v[1].w) + v[2].w;

    __shared__ __align__(16) float4 sred[NT_B];
    __shared__ float fred[128];
    __shared__ int last;
    sred[t] = s;
    __syncthreads();
    // fixed-order tree over the chunk dimension (stride 32 in t)
#pragma unroll
    for (int off = 512; off >= 32; off >>= 1) {
        if (t < off) {
            sred[t].x += sred[t + off].x;  sred[t].y += sred[t + off].y;
            sred[t].z += sred[t + off].z;  sred[t].w += sred[t + off].w;
        }
        __syncthreads();
    }

    // threads 0..31 hold complete sums for their quad
    float term = 0.f;
    if (t < 32) {
        const float4 a4 = sred[t];
        const float ax = a4.x * (1.f / (float)NROW);
        const float ay = a4.y * (1.f / (float)NROW);
        const float az = a4.z * (1.f / (float)NROW);
        const float aw = a4.w * (1.f / (float)NROW);
        term = ax * logf(ax + 1e-5f) + ay * logf(ay + 1e-5f) +
               az * logf(az + 1e-5f) + aw * logf(aw + 1e-5f);
#pragma unroll
        for (int off = 16; off > 0; off >>= 1)
            term += __shfl_down_sync(0xFFFFFFFFu, term, off);
        if (t == 0) {
            const long long vfx = __double2ll_rn((double)term * FIX_SCALE);
            atomicAdd(&g_accT, (unsigned long long)vfx);
            __threadfence();
            last = (atomicAdd(&g_ticket, 1u) == NBLK_B - 1) ? 1 : 0;
        }
    }
    __syncthreads();
    if (!last) return;

    // final block: assemble scalars (74-wide sums via 128-thread tree)
    if (t < 128) fred[t] = (t < RG) ? g_pH[t] : 0.f;
    __syncthreads();
#pragma unroll
    for (int off = 64; off > 0; off >>= 1) {
        if (t < off) fred[t] += fred[t + off];
        __syncthreads();
    }
    const float sumH = fred[0];
    __syncthreads();
    if (t < 128) fred[t] = (t < RG) ? g_pC[t] : 0.f;
    __syncthreads();
#pragma unroll
    for (int off = 64; off > 0; off >>= 1) {
        if (t < off) fred[t] += fred[t + off];
        __syncthreads();
    }
    const float sumC = fred[0];

    if (t == 0) {
        const long long tot = (long long)atomicAdd(&g_accT, 0ull);
        const float sumT = (float)((double)tot * (1.0 / FIX_SCALE));
        const float per_sample = sumH * (1.f / (float)NROW);
        const float cb_entropy = -sumT;
        float* sc = out + NROW * NDIM + NROW;
        sc[0] = per_sample;
        sc[1] = cb_entropy;
        sc[2] = per_sample - cb_entropy;
        sc[3] = sumC * (1.f / (float)(NROW * NDIM));
    }
}

extern "C" void kernel_launch(void* const* d_in, const int* in_sizes, int n_in,
                              void* d_out, int out_size)
{
    (void)in_sizes; (void)n_in; (void)out_size;
    const float* x = (const float*)d_in[0];   // [2,2048,14] float32
    float* out = (float*)d_out;

    cudaFuncSetAttribute(lfq_rows_kernel,
                         cudaFuncAttributeMaxDynamicSharedMemorySize, SMEM_BYTES);
    lfq_rows_kernel<<<GRID_A, NT_A, SMEM_BYTES>>>(x, out);
    lfq_reduce_kernel<<<NBLK_B, NT_B>>>(out);
}

// round 11
// speedup vs baseline: 1.0204x; 1.0204x over previous
#include <cuda_runtime.h>

// LFQ quantizer, factorized-softmax formulation, v7.
// v6 -> v7: reduce kernel gets its MLP from occupancy, not per-thread regs:
//   128 blocks x 1024 threads, 32 chunks x <=3 rgs/thread, 3 float4 in regs.
//
// probs_j = prod_d sigmoid(400*s_d(j)*x_d) = f(lo 8 bits) * g(hi 6 bits).
// avg_probs = (1/4096) F^T G computed as split-K rank-1 accumulation.

#define RG      74          // row groups
#define RPB     56          // rows per group (last group has 8 valid)
#define GRID_A  (RG * 4)    // 296 blocks = 2 x 148 SMs
#define NT_A    512
#define NCODES  16384
#define NROW    4096
#define NDIM    14
#define NBLK_B  128
#define NT_B    1024

// scratch (__device__ globals; no allocations allowed)
__device__ float g_partial[RG * NCODES];           // 4.85 MB split-K partials
__device__ float g_pH[RG];
__device__ float g_pC[RG];
__device__ unsigned long long g_accT;              // fixed-point sum of a*log(a+eps)
__device__ unsigned int g_ticket;

#define FIX_SCALE 1099511627776.0   // 2^40

// dynamic smem layout (floats)
#define OF_F    0                     // f  [RPB][256]
#define OF_SG   (RPB * 256)           // sg [RPB][64]
#define OF_SQ   (OF_SG + RPB * 64)    // sq [RPB][NDIM][2]
#define OF_F03  (OF_SQ + RPB * NDIM * 2)  // f03 [RPB][16]
#define OF_F47  (OF_F03 + RPB * 16)       // f47 [RPB][16]
#define OF_WH   (OF_F47 + RPB * 16)       // swH [16]
#define OF_WC   (OF_WH + 16)              // swC [16]
#define SMEM_FLOATS (OF_WC + 16)
#define SMEM_BYTES  (SMEM_FLOATS * 4)

__global__ __launch_bounds__(NT_A, 2) void lfq_rows_kernel(const float* __restrict__ x,
                                                           float* __restrict__ out)
{
    extern __shared__ __align__(16) float sm[];
    float* F   = sm + OF_F;     // [RPB][256]
    float* SG  = sm + OF_SG;    // [RPB][64]
    float* SQ  = sm + OF_SQ;    // [RPB][NDIM][2]
    float* F03 = sm + OF_F03;   // [RPB][16]
    float* F47 = sm + OF_F47;
    float* SWH = sm + OF_WH;
    float* SWC = sm + OF_WC;

    const int t  = threadIdx.x;
    const int b  = blockIdx.x;
    const int rg = b >> 2;          // row group
    const int h  = b & 3;           // hi quarter
    const int row0  = rg * RPB;
    const int valid = min(RPB, NROW - row0);

    // reset cross-kernel accumulators (visible to kernel B via launch boundary)
    if (b == 0 && t == 0) { g_accT = 0ull; g_ticket = 0u; }

    // ---- phase 0: per-element Bernoulli tables; h==0 also emits outputs/H/C ----
    float hS = 0.f, cS = 0.f;
#pragma unroll
    for (int k = 0; k < 2; k++) {
        const int e = t + NT_A * k;             // covers RPB*NDIM = 784
        if (e < RPB * NDIM) {
            const int row = e / NDIM;
            if (row < valid) {
                const int d = e - row * NDIM;
                const float xv = x[(row0 + row) * NDIM + d];
                const int pos = xv > 0.f ? 1 : 0;
                const float au = fabsf(400.f * xv);
                const float ee = __expf(-au);                  // e^{-|u|}
                const float qmaj = __fdividef(1.f, 1.f + ee);  // sigmoid(|u|)
                const float qmin = ee * qmaj;                  // sigmoid(-|u|)
                SQ[(row * NDIM + d) * 2 + pos]     = qmaj;
                SQ[(row * NDIM + d) * 2 + 1 - pos] = qmin;
                if (h == 0) {
                    hS += log1pf(ee) + qmin * au;              // binary entropy (nats)
                    const float cm = fabsf(xv) - 1.f;
                    cS += cm * cm;
                    out[(row0 + row) * NDIM + d] = pos ? 1.f : -1.f;
                }
            } else {
                const int d = e - row * NDIM;
                SQ[(row * NDIM + d) * 2 + 0] = 0.f;
                SQ[(row * NDIM + d) * 2 + 1] = 0.f;
            }
        }
    }
    if (h == 0) {
        // big-endian packed index, one thread per row
        if (t < valid) {
            int idx = 0;
#pragma unroll
            for (int d = 0; d < NDIM; d++)
                idx |= (x[(row0 + t) * NDIM + d] > 0.f) ? (1 << (13 - d)) : 0;
            out[NROW * NDIM + row0 + t] = (float)idx;
        }
        // warp-level H/C reduce
#pragma unroll
        for (int off = 16; off > 0; off >>= 1) {
            hS += __shfl_down_sync(0xFFFFFFFFu, hS, off);
            cS += __shfl_down_sync(0xFFFFFFFFu, cS, off);
        }
        if ((t & 31) == 0) { SWH[t >> 5] = hS; SWC[t >> 5] = cS; }
    }
    __syncthreads();

    // ---- phase A1: f03 / f47 sub-products ----
#pragma unroll
    for (int k = 0; k < 4; k++) {
        const int e = t + NT_A * k;             // covers [0, 2048) >= 2*RPB*16 = 1792
        if (e < RPB * 16) {
            const int row = e >> 4, i = e & 15;
            const float* q = SQ + row * NDIM * 2;
            F03[e] = q[0 * 2 + (i & 1)] * q[1 * 2 + ((i >> 1) & 1)] *
                     q[2 * 2 + ((i >> 2) & 1)] * q[3 * 2 + ((i >> 3) & 1)];
        } else if (e < 2 * RPB * 16) {
            const int e2 = e - RPB * 16;
            const int row = e2 >> 4, i = e2 & 15;
            const float* q = SQ + row * NDIM * 2;
            F47[e2] = q[4 * 2 + (i & 1)] * q[5 * 2 + ((i >> 1) & 1)] *
                      q[6 * 2 + ((i >> 2) & 1)] * q[7 * 2 + ((i >> 3) & 1)];
        }
    }
    __syncthreads();

    // ---- phase A2: full f table + g table (exact coverage, no guards) ----
#pragma unroll
    for (int k = 0; k < 28; k++) {
        const int e = t + NT_A * k;             // RPB*256 = 14336 = 28*512
        const int row = e >> 8, lo = e & 255;
        F[e] = F03[row * 16 + (lo & 15)] * F47[row * 16 + (lo >> 4)];
    }
#pragma unroll
    for (int k = 0; k < 7; k++) {
        const int e = t + NT_A * k;             // RPB*64 = 3584 = 7*512
        const int row = e >> 6, hc = e & 63;
        const float* q = SQ + row * NDIM * 2;
        SG[e] = q[8 * 2 + (hc & 1)] * q[9 * 2 + ((hc >> 1) & 1)] *
                q[10 * 2 + ((hc >> 2) & 1)] * q[11 * 2 + ((hc >> 3) & 1)] *
                q[12 * 2 + ((hc >> 4) & 1)] * q[13 * 2 + ((hc >> 5) & 1)];
    }
    __syncthreads();

    // ---- phase B: barrier-free rank-1 accumulation (FMA-bound) ----
    const int p   = t & 127;                    // lo pair: lo = 2p, 2p+1
    const int sub = t >> 7;                     // 0..3
    const int hi0 = h * 16 + sub * 4;           // this thread's 4 hi values

    float2 acc[4];
#pragma unroll
    for (int k = 0; k < 4; k++) acc[k] = make_float2(0.f, 0.f);

#pragma unroll 4
    for (int r = 0; r < valid; r++) {
        const float2 fp = *reinterpret_cast<const float2*>(F + r * 256 + 2 * p);  // LDS.64
        const float4 gv = *reinterpret_cast<const float4*>(SG + r * 64 + hi0);    // LDS.128 bcast
        acc[0].x = fmaf(fp.x, gv.x, acc[0].x);  acc[0].y = fmaf(fp.y, gv.x, acc[0].y);
        acc[1].x = fmaf(fp.x, gv.y, acc[1].x);  acc[1].y = fmaf(fp.y, gv.y, acc[1].y);
        acc[2].x = fmaf(fp.x, gv.z, acc[2].x);  acc[2].y = fmaf(fp.y, gv.z, acc[2].y);
        acc[3].x = fmaf(fp.x, gv.w, acc[3].x);  acc[3].y = fmaf(fp.y, gv.w, acc[3].y);
    }

    // store partials: code j = hi*256 + lo
    float2* gp = reinterpret_cast<float2*>(g_partial + rg * NCODES);
#pragma unroll
    for (int k = 0; k < 4; k++)
        gp[((hi0 + k) * 256 + 2 * p) >> 1] = acc[k];

    if (h == 0 && t == 0) {
        float H = 0.f, C = 0.f;
#pragma unroll
        for (int w = 0; w < 16; w++) { H += SWH[w]; C += SWC[w]; }
        g_pH[rg] = H; g_pC[rg] = C;
    }
}

// Reduce: 128 blocks x 1024 threads. Thread = (quad, chunk).
//   quad  = blockIdx.x*32 + (t & 31)   -> 4 consecutive codes (float4)
//   chunk = t >> 5  (0..31)            -> rgs {chunk*3 + k, k<3} ∩ [0,74)
// 32 warps/SM of 3-deep float4 loads => ~4.5 MB in flight chip-wide.
__global__ __launch_bounds__(NT_B, 1) void lfq_reduce_kernel(float* __restrict__ out)
{
    const int t = threadIdx.x;
    const int quad  = blockIdx.x * 32 + (t & 31);
    const int chunk = t >> 5;
    const int rg0 = chunk * 3;

    const float4* gp = reinterpret_cast<const float4*>(g_partial) + quad;

    float4 v[3];
#pragma unroll
    for (int k = 0; k < 3; k++) {
        v[k] = make_float4(0.f, 0.f, 0.f, 0.f);
        if (rg0 + k < RG)
            v[k] = gp[(rg0 + k) * (NCODES / 4)];   // LDG.128, 512B/warp coalesced
    }

    float4 s;
    s.x = (v[0].x + v[1].x) + v[2].x;
    s.y = (v[0].y + v[1].y) + v[2].y;
    s.z = (v[0].z + v[1].z) + v[2].z;
    s.w = (v[0].w + v[1].w) + v[2].w;

    __shared__ __align__(16) float4 sred[NT_B];
    __shared__ float fred[128];
    __shared__ int last;
    sred[t] = s;
    __syncthreads();
    // fixed-order tree over the chunk dimension (stride 32 in t)
#pragma unroll
    for (int off = 512; off >= 32; off >>= 1) {
        if (t < off) {
            sred[t].x += sred[t + off].x;  sred[t].y += sred[t + off].y;
            sred[t].z += sred[t + off].z;  sred[t].w += sred[t + off].w;
        }
        __syncthreads();
    }

    // threads 0..31 hold complete sums for their quad
    float term = 0.f;
    if (t < 32) {
        const float4 a4 = sred[t];
        const float ax = a4.x * (1.f / (float)NROW);
        const float ay = a4.y * (1.f / (float)NROW);
        const float az = a4.z * (1.f / (float)NROW);
        const float aw = a4.w * (1.f / (float)NROW);
        term = ax * logf(ax + 1e-5f) + ay * logf(ay + 1e-5f) +
               az * logf(az + 1e-5f) + aw * logf(aw + 1e-5f);
#pragma unroll
        for (int off = 16; off > 0; off >>= 1)
            term += __shfl_down_sync(0xFFFFFFFFu, term, off);
        if (t == 0) {
            const long long vfx = __double2ll_rn((double)term * FIX_SCALE);
            atomicAdd(&g_accT, (unsigned long long)vfx);
            __threadfence();
            last = (atomicAdd(&g_ticket, 1u) == NBLK_B - 1) ? 1 : 0;
        }
    }
    __syncthreads();
    if (!last) return;

    // final block: assemble scalars (74-wide sums via 128-thread tree)
    if (t < 128) fred[t] = (t < RG) ? g_pH[t] : 0.f;
    __syncthreads();
#pragma unroll
    for (int off = 64; off > 0; off >>= 1) {
        if (t < off) fred[t] += fred[t + off];
        __syncthreads();
    }
    const float sumH = fred[0];
    __syncthreads();
    if (t < 128) fred[t] = (t < RG) ? g_pC[t] : 0.f;
    __syncthreads();
#pragma unroll
    for (int off = 64; off > 0; off >>= 1) {
        if (t < off) fred[t] += fred[t + off];
        __syncthreads();
    }
    const float sumC = fred[0];

    if (t == 0) {
        const long long tot = (long long)atomicAdd(&g_accT, 0ull);
        const float sumT = (float)((double)tot * (1.0 / FIX_SCALE));
        const float per_sample = sumH * (1.f / (float)NROW);
        const float cb_entropy = -sumT;
        float* sc = out + NROW * NDIM + NROW;
        sc[0] = per_sample;
        sc[1] = cb_entropy;
        sc[2] = per_sample - cb_entropy;
        sc[3] = sumC * (1.f / (float)(NROW * NDIM));
    }
}

extern "C" void kernel_launch(void* const* d_in, const int* in_sizes, int n_in,
                              void* d_out, int out_size)
{
    (void)in_sizes; (void)n_in; (void)out_size;
    const float* x = (const float*)d_in[0];   // [2,2048,14] float32
    float* out = (float*)d_out;

    cudaFuncSetAttribute(lfq_rows_kernel,
                         cudaFuncAttributeMaxDynamicSharedMemorySize, SMEM_BYTES);
    lfq_rows_kernel<<<GRID_A, NT_A, SMEM_BYTES>>>(x, out);
    lfq_reduce_kernel<<<NBLK_B, NT_B>>>(out);
}

// round 12
// speedup vs baseline: 1.0221x; 1.0017x over previous
#include <cuda_runtime.h>

// LFQ quantizer, factorized-softmax formulation, v7.
// v6 -> v7: reduce kernel gets its MLP from occupancy, not per-thread regs:
//   128 blocks x 1024 threads, 32 chunks x <=3 rgs/thread, 3 float4 in regs.
//
// probs_j = prod_d sigmoid(400*s_d(j)*x_d) = f(lo 8 bits) * g(hi 6 bits).
// avg_probs = (1/4096) F^T G computed as split-K rank-1 accumulation.

#define RG      74          // row groups
#define RPB     56          // rows per group (last group has 8 valid)
#define GRID_A  (RG * 4)    // 296 blocks = 2 x 148 SMs
#define NT_A    512
#define NCODES  16384
#define NROW    4096
#define NDIM    14
#define NBLK_B  128
#define NT_B    1024

// scratch (__device__ globals; no allocations allowed)
__device__ float g_partial[RG * NCODES];           // 4.85 MB split-K partials
__device__ float g_pH[RG];
__device__ float g_pC[RG];
__device__ unsigned long long g_accT;              // fixed-point sum of a*log(a+eps)
__device__ unsigned int g_ticket;

#define FIX_SCALE 1099511627776.0   // 2^40

// dynamic smem layout (floats)
#define OF_F    0                     // f  [RPB][256]
#define OF_SG   (RPB * 256)           // sg [RPB][64]
#define OF_SQ   (OF_SG + RPB * 64)    // sq [RPB][NDIM][2]
#define OF_F03  (OF_SQ + RPB * NDIM * 2)  // f03 [RPB][16]
#define OF_F47  (OF_F03 + RPB * 16)       // f47 [RPB][16]
#define OF_WH   (OF_F47 + RPB * 16)       // swH [16]
#define OF_WC   (OF_WH + 16)              // swC [16]
#define SMEM_FLOATS (OF_WC + 16)
#define SMEM_BYTES  (SMEM_FLOATS * 4)

__global__ __launch_bounds__(NT_A, 2) void lfq_rows_kernel(const float* __restrict__ x,
                                                           float* __restrict__ out)
{
    extern __shared__ __align__(16) float sm[];
    float* F   = sm + OF_F;     // [RPB][256]
    float* SG  = sm + OF_SG;    // [RPB][64]
    float* SQ  = sm + OF_SQ;    // [RPB][NDIM][2]
    float* F03 = sm + OF_F03;   // [RPB][16]
    float* F47 = sm + OF_F47;
    float* SWH = sm + OF_WH;
    float* SWC = sm + OF_WC;

    const int t  = threadIdx.x;
    const int b  = blockIdx.x;
    const int rg = b >> 2;          // row group
    const int h  = b & 3;           // hi quarter
    const int row0  = rg * RPB;
    const int valid = min(RPB, NROW - row0);

    // reset cross-kernel accumulators (visible to kernel B via launch boundary)
    if (b == 0 && t == 0) { g_accT = 0ull; g_ticket = 0u; }

    // ---- phase 0: per-element Bernoulli tables; h==0 also emits outputs/H/C ----
    float hS = 0.f, cS = 0.f;
#pragma unroll
    for (int k = 0; k < 2; k++) {
        const int e = t + NT_A * k;             // covers RPB*NDIM = 784
        if (e < RPB * NDIM) {
            const int row = e / NDIM;
            if (row < valid) {
                const int d = e - row * NDIM;
                const float xv = x[(row0 + row) * NDIM + d];
                const int pos = xv > 0.f ? 1 : 0;
                const float au = fabsf(400.f * xv);
                const float ee = __expf(-au);                  // e^{-|u|}
                const float qmaj = __fdividef(1.f, 1.f + ee);  // sigmoid(|u|)
                const float qmin = ee * qmaj;                  // sigmoid(-|u|)
                SQ[(row * NDIM + d) * 2 + pos]     = qmaj;
                SQ[(row * NDIM + d) * 2 + 1 - pos] = qmin;
                if (h == 0) {
                    hS += log1pf(ee) + qmin * au;              // binary entropy (nats)
                    const float cm = fabsf(xv) - 1.f;
                    cS += cm * cm;
                    out[(row0 + row) * NDIM + d] = pos ? 1.f : -1.f;
                }
            } else {
                const int d = e - row * NDIM;
                SQ[(row * NDIM + d) * 2 + 0] = 0.f;
                SQ[(row * NDIM + d) * 2 + 1] = 0.f;
            }
        }
    }
    if (h == 0) {
        // big-endian packed index, one thread per row
        if (t < valid) {
            int idx = 0;
#pragma unroll
            for (int d = 0; d < NDIM; d++)
                idx |= (x[(row0 + t) * NDIM + d] > 0.f) ? (1 << (13 - d)) : 0;
            out[NROW * NDIM + row0 + t] = (float)idx;
        }
        // warp-level H/C reduce
#pragma unroll
        for (int off = 16; off > 0; off >>= 1) {
            hS += __shfl_down_sync(0xFFFFFFFFu, hS, off);
            cS += __shfl_down_sync(0xFFFFFFFFu, cS, off);
        }
        if ((t & 31) == 0) { SWH[t >> 5] = hS; SWC[t >> 5] = cS; }
    }
    __syncthreads();

    // ---- phase A1: f03 / f47 sub-products ----
#pragma unroll
    for (int k = 0; k < 4; k++) {
        const int e = t + NT_A * k;             // covers [0, 2048) >= 2*RPB*16 = 1792
        if (e < RPB * 16) {
            const int row = e >> 4, i = e & 15;
            const float* q = SQ + row * NDIM * 2;
            F03[e] = q[0 * 2 + (i & 1)] * q[1 * 2 + ((i >> 1) & 1)] *
                     q[2 * 2 + ((i >> 2) & 1)] * q[3 * 2 + ((i >> 3) & 1)];
        } else if (e < 2 * RPB * 16) {
            const int e2 = e - RPB * 16;
            const int row = e2 >> 4, i = e2 & 15;
            const float* q = SQ + row * NDIM * 2;
            F47[e2] = q[4 * 2 + (i & 1)] * q[5 * 2 + ((i >> 1) & 1)] *
                      q[6 * 2 + ((i >> 2) & 1)] * q[7 * 2 + ((i >> 3) & 1)];
        }
    }
    __syncthreads();

    // ---- phase A2: full f table + g table (exact coverage, no guards) ----
#pragma unroll
    for (int k = 0; k < 28; k++) {
        const int e = t + NT_A * k;             // RPB*256 = 14336 = 28*512
        const int row = e >> 8, lo = e & 255;
        F[e] = F03[row * 16 + (lo & 15)] * F47[row * 16 + (lo >> 4)];
    }
#pragma unroll
    for (int k = 0; k < 7; k++) {
        const int e = t + NT_A * k;             // RPB*64 = 3584 = 7*512
        const int row = e >> 6, hc = e & 63;
        const float* q = SQ + row * NDIM * 2;
        SG[e] = q[8 * 2 + (hc & 1)] * q[9 * 2 + ((hc >> 1) & 1)] *
                q[10 * 2 + ((hc >> 2) & 1)] * q[11 * 2 + ((hc >> 3) & 1)] *
                q[12 * 2 + ((hc >> 4) & 1)] * q[13 * 2 + ((hc >> 5) & 1)];
    }
    __syncthreads();

    // ---- phase B: barrier-free rank-1 accumulation (FMA-bound) ----
    const int p   = t & 127;                    // lo pair: lo = 2p, 2p+1
    const int sub = t >> 7;                     // 0..3
    const int hi0 = h * 16 + sub * 4;           // this thread's 4 hi values

    float2 acc[4];
#pragma unroll
    for (int k = 0; k < 4; k++) acc[k] = make_float2(0.f, 0.f);

#pragma unroll 4
    for (int r = 0; r < valid; r++) {
        const float2 fp = *reinterpret_cast<const float2*>(F + r * 256 + 2 * p);  // LDS.64
        const float4 gv = *reinterpret_cast<const float4*>(SG + r * 64 + hi0);    // LDS.128 bcast
        acc[0].x = fmaf(fp.x, gv.x, acc[0].x);  acc[0].y = fmaf(fp.y, gv.x, acc[0].y);
        acc[1].x = fmaf(fp.x, gv.y, acc[1].x);  acc[1].y = fmaf(fp.y, gv.y, acc[1].y);
        acc[2].x = fmaf(fp.x, gv.z, acc[2].x);  acc[2].y = fmaf(fp.y, gv.z, acc[2].y);
        acc[3].x = fmaf(fp.x, gv.w, acc[3].x);  acc[3].y = fmaf(fp.y, gv.w, acc[3].y);
    }

    // store partials: code j = hi*256 + lo
    float2* gp = reinterpret_cast<float2*>(g_partial + rg * NCODES);
#pragma unroll
    for (int k = 0; k < 4; k++)
        gp[((hi0 + k) * 256 + 2 * p) >> 1] = acc[k];

    if (h == 0 && t == 0) {
        float H = 0.f, C = 0.f;
#pragma unroll
        for (int w = 0; w < 16; w++) { H += SWH[w]; C += SWC[w]; }
        g_pH[rg] = H; g_pC[rg] = C;
    }
}

// Reduce: 128 blocks x 1024 threads. Thread = (quad, chunk).
//   quad  = blockIdx.x*32 + (t & 31)   -> 4 consecutive codes (float4)
//   chunk = t >> 5  (0..31)            -> rgs {chunk*3 + k, k<3} ∩ [0,74)
// 32 warps/SM of 3-deep float4 loads => ~4.5 MB in flight chip-wide.
__global__ __launch_bounds__(NT_B, 1) void lfq_reduce_kernel(float* __restrict__ out)
{
    const int t = threadIdx.x;
    const int quad  = blockIdx.x * 32 + (t & 31);
    const int chunk = t >> 5;
    const int rg0 = chunk * 3;

    const float4* gp = reinterpret_cast<const float4*>(g_partial) + quad;

    float4 v[3];
#pragma unroll
    for (int k = 0; k < 3; k++) {
        v[k] = make_float4(0.f, 0.f, 0.f, 0.f);
        if (rg0 + k < RG)
            v[k] = gp[(rg0 + k) * (NCODES / 4)];   // LDG.128, 512B/warp coalesced
    }

    float4 s;
    s.x = (v[0].x + v[1].x) + v[2].x;
    s.y = (v[0].y + v[1].y) + v[2].y;
    s.z = (v[0].z + v[1].z) + v[2].z;
    s.w = (v[0].w + v[1].w) + v[2].w;

    __shared__ __align__(16) float4 sred[NT_B];
    __shared__ float fred[128];
    __shared__ int last;
    sred[t] = s;
    __syncthreads();
    // fixed-order tree over the chunk dimension (stride 32 in t)
#pragma unroll
    for (int off = 512; off >= 32; off >>= 1) {
        if (t < off) {
            sred[t].x += sred[t + off].x;  sred[t].y += sred[t + off].y;
            sred[t].z += sred[t + off].z;  sred[t].w += sred[t + off].w;
        }
        __syncthreads();
    }

    // threads 0..31 hold complete sums for their quad
    float term = 0.f;
    if (t < 32) {
        const float4 a4 = sred[t];
        const float ax = a4.x * (1.f / (float)NROW);
        const float ay = a4.y * (1.f / (float)NROW);
        const float az = a4.z * (1.f / (float)NROW);
        const float aw = a4.w * (1.f / (float)NROW);
        term = ax * logf(ax + 1e-5f) + ay * logf(ay + 1e-5f) +
               az * logf(az + 1e-5f) + aw * logf(aw + 1e-5f);
#pragma unroll
        for (int off = 16; off > 0; off >>= 1)
            term += __shfl_down_sync(0xFFFFFFFFu, term, off);
        if (t == 0) {
            const long long vfx = __double2ll_rn((double)term * FIX_SCALE);
            atomicAdd(&g_accT, (unsigned long long)vfx);
            __threadfence();
            last = (atomicAdd(&g_ticket, 1u) == NBLK_B - 1) ? 1 : 0;
        }
    }
    __syncthreads();
    if (!last) return;

    // final block: assemble scalars (74-wide sums via 128-thread tree)
    if (t < 128) fred[t] = (t < RG) ? g_pH[t] : 0.f;
    __syncthreads();
#pragma unroll
    for (int off = 64; off > 0; off >>= 1) {
        if (t < off) fred[t] += fred[t + off];
        __syncthreads();
    }
    const float sumH = fred[0];
    __syncthreads();
    if (t < 128) fred[t] = (t < RG) ? g_pC[t] : 0.f;
    __syncthreads();
#pragma unroll
    for (int off = 64; off > 0; off >>= 1) {
        if (t < off) fred[t] += fred[t + off];
        __syncthreads();
    }
    const float sumC = fred[0];

    if (t == 0) {
        const long long tot = (long long)atomicAdd(&g_accT, 0ull);
        const float sumT = (float)((double)tot * (1.0 / FIX_SCALE));
        const float per_sample = sumH * (1.f / (float)NROW);
        const float cb_entropy = -sumT;
        float* sc = out + NROW * NDIM + NROW;
        sc[0] = per_sample;
        sc[1] = cb_entropy;
        sc[2] = per_sample - cb_entropy;
        sc[3] = sumC * (1.f / (float)(NROW * NDIM));
    }
}

extern "C" void kernel_launch(void* const* d_in, const int* in_sizes, int n_in,
                              void* d_out, int out_size)
{
    (void)in_sizes; (void)n_in; (void)out_size;
    const float* x = (const float*)d_in[0];   // [2,2048,14] float32
    float* out = (float*)d_out;

    cudaFuncSetAttribute(lfq_rows_kernel,
                         cudaFuncAttributeMaxDynamicSharedMemorySize, SMEM_BYTES);
    lfq_rows_kernel<<<GRID_A, NT_A, SMEM_BYTES>>>(x, out);
    lfq_reduce_kernel<<<NBLK_B, NT_B>>>(out);
}

// round 13
// speedup vs baseline: 1.0363x; 1.0138x over previous
#include <cuda_runtime.h>

// LFQ quantizer, factorized-softmax formulation, v8.
// v7 -> v8: the multi-MB split-K partial matrix is eliminated. Rows kernel
// RED.F32-accumulates avg_probs directly into g_avg[16384] (64 KB); the
// finalize kernel reads 64 KB, computes the entropy scalar, and resets all
// cross-replay state.
//
// probs_j = prod_d sigmoid(400*s_d(j)*x_d) = f(lo 8 bits) * g(hi 6 bits).

#define RG      37          // row groups
#define RPB     112         // rows per group (last group: 64 valid)
#define GRID_A  (RG * 4)    // 148 blocks = 1 per SM
#define NT_A    512
#define NCODES  16384
#define NROW    4096
#define NDIM    14
#define NBLK_F  32
#define NT_F    512

// scratch (__device__ globals; zero-initialized at load; no allocations allowed)
__device__ float g_avg[NCODES];                    // RED-accumulated sum of probs
__device__ float g_pH[RG];
__device__ float g_pC[RG];
__device__ unsigned long long g_accT;              // fixed-point sum of a*log(a+eps)
__device__ unsigned int g_ticket;

#define FIX_SCALE 1099511627776.0   // 2^40

// dynamic smem layout (floats)
#define OF_F    0                         // F  [RPB][256]
#define OF_SG   (RPB * 256)               // SG [RPB][64]
#define OF_SQ   (OF_SG + RPB * 64)        // SQ [RPB][NDIM][2]
#define OF_F03  (OF_SQ + RPB * NDIM * 2)  // F03 [RPB][16]
#define OF_F47  (OF_F03 + RPB * 16)       // F47 [RPB][16]
#define OF_WH   (OF_F47 + RPB * 16)       // SWH [16]
#define OF_WC   (OF_WH + 16)              // SWC [16]
#define SMEM_FLOATS (OF_WC + 16)
#define SMEM_BYTES  (SMEM_FLOATS * 4)     // ~167 KB -> 1 CTA/SM

__global__ __launch_bounds__(NT_A, 1) void lfq_rows_kernel(const float* __restrict__ x,
                                                           float* __restrict__ out)
{
    extern __shared__ __align__(16) float sm[];
    float* F   = sm + OF_F;     // [RPB][256]
    float* SG  = sm + OF_SG;    // [RPB][64]
    float* SQ  = sm + OF_SQ;    // [RPB][NDIM][2]
    float* F03 = sm + OF_F03;   // [RPB][16]
    float* F47 = sm + OF_F47;
    float* SWH = sm + OF_WH;
    float* SWC = sm + OF_WC;

    const int t  = threadIdx.x;
    const int b  = blockIdx.x;
    const int rg = b >> 2;          // row group 0..36
    const int h  = b & 3;           // hi quarter
    const int row0  = rg * RPB;
    const int valid = min(RPB, NROW - row0);

    // ---- phase 0: per-element Bernoulli tables; h==0 also emits outputs/H/C ----
    float hS = 0.f, cS = 0.f;
#pragma unroll
    for (int k = 0; k < 4; k++) {
        const int e = t + NT_A * k;             // covers RPB*NDIM = 1568
        if (e < RPB * NDIM) {
            const int row = e / NDIM;
            const int d = e - row * NDIM;
            if (row < valid) {
                const float xv = x[(row0 + row) * NDIM + d];
                const int pos = xv > 0.f ? 1 : 0;
                const float au = fabsf(400.f * xv);
                const float ee = __expf(-au);                  // e^{-|u|}
                const float qmaj = __fdividef(1.f, 1.f + ee);  // sigmoid(|u|)
                const float qmin = ee * qmaj;                  // sigmoid(-|u|)
                SQ[(row * NDIM + d) * 2 + pos]     = qmaj;
                SQ[(row * NDIM + d) * 2 + 1 - pos] = qmin;
                if (h == 0) {
                    hS += log1pf(ee) + qmin * au;              // binary entropy (nats)
                    const float cm = fabsf(xv) - 1.f;
                    cS += cm * cm;
                    out[(row0 + row) * NDIM + d] = pos ? 1.f : -1.f;
                }
            } else {
                SQ[(row * NDIM + d) * 2 + 0] = 0.f;
                SQ[(row * NDIM + d) * 2 + 1] = 0.f;
            }
        }
    }
    if (h == 0) {
        // big-endian packed index, one thread per row (L1-hit reloads)
        if (t < valid) {
            int idx = 0;
#pragma unroll
            for (int d = 0; d < NDIM; d++)
                idx |= (x[(row0 + t) * NDIM + d] > 0.f) ? (1 << (13 - d)) : 0;
            out[NROW * NDIM + row0 + t] = (float)idx;
        }
        // warp-level H/C reduce
#pragma unroll
        for (int off = 16; off > 0; off >>= 1) {
            hS += __shfl_down_sync(0xFFFFFFFFu, hS, off);
            cS += __shfl_down_sync(0xFFFFFFFFu, cS, off);
        }
        if ((t & 31) == 0) { SWH[t >> 5] = hS; SWC[t >> 5] = cS; }
    }
    __syncthreads();

    // ---- phase A1: f03 / f47 sub-products (2*RPB*16 = 3584 = 7*512, exact) ----
#pragma unroll
    for (int k = 0; k < 7; k++) {
        const int e = t + NT_A * k;
        if (e < RPB * 16) {
            const int row = e >> 4, i = e & 15;
            const float* q = SQ + row * NDIM * 2;
            F03[e] = q[0 * 2 + (i & 1)] * q[1 * 2 + ((i >> 1) & 1)] *
                     q[2 * 2 + ((i >> 2) & 1)] * q[3 * 2 + ((i >> 3) & 1)];
        } else {
            const int e2 = e - RPB * 16;
            const int row = e2 >> 4, i = e2 & 15;
            const float* q = SQ + row * NDIM * 2;
            F47[e2] = q[4 * 2 + (i & 1)] * q[5 * 2 + ((i >> 1) & 1)] *
                      q[6 * 2 + ((i >> 2) & 1)] * q[7 * 2 + ((i >> 3) & 1)];
        }
    }
    __syncthreads();

    // ---- phase A2: full f table + g table (exact coverage) ----
#pragma unroll
    for (int k = 0; k < 56; k++) {
        const int e = t + NT_A * k;             // RPB*256 = 28672 = 56*512
        const int row = e >> 8, lo = e & 255;
        F[e] = F03[row * 16 + (lo & 15)] * F47[row * 16 + (lo >> 4)];
    }
#pragma unroll
    for (int k = 0; k < 14; k++) {
        const int e = t + NT_A * k;             // RPB*64 = 7168 = 14*512
        const int row = e >> 6, hc = e & 63;
        const float* q = SQ + row * NDIM * 2;
        SG[e] = q[8 * 2 + (hc & 1)] * q[9 * 2 + ((hc >> 1) & 1)] *
                q[10 * 2 + ((hc >> 2) & 1)] * q[11 * 2 + ((hc >> 3) & 1)] *
                q[12 * 2 + ((hc >> 4) & 1)] * q[13 * 2 + ((hc >> 5) & 1)];
    }
    __syncthreads();

    // ---- phase B: barrier-free rank-1 accumulation (FMA-bound) ----
    const int p   = t & 127;                    // lo pair: lo = 2p, 2p+1
    const int sub = t >> 7;                     // 0..3
    const int hi0 = h * 16 + sub * 4;           // this thread's 4 hi values

    float2 acc[4];
#pragma unroll
    for (int k = 0; k < 4; k++) acc[k] = make_float2(0.f, 0.f);

#pragma unroll 4
    for (int r = 0; r < valid; r++) {
        const float2 fp = *reinterpret_cast<const float2*>(F + r * 256 + 2 * p);  // LDS.64
        const float4 gv = *reinterpret_cast<const float4*>(SG + r * 64 + hi0);    // LDS.128 bcast
        acc[0].x = fmaf(fp.x, gv.x, acc[0].x);  acc[0].y = fmaf(fp.y, gv.x, acc[0].y);
        acc[1].x = fmaf(fp.x, gv.y, acc[1].x);  acc[1].y = fmaf(fp.y, gv.y, acc[1].y);
        acc[2].x = fmaf(fp.x, gv.z, acc[2].x);  acc[2].y = fmaf(fp.y, gv.z, acc[2].y);
        acc[3].x = fmaf(fp.x, gv.w, acc[3].x);  acc[3].y = fmaf(fp.y, gv.w, acc[3].y);
    }

    // fire-and-forget RED accumulation into the 64 KB avg_probs vector
#pragma unroll
    for (int k = 0; k < 4; k++) {
        const int j = (hi0 + k) * 256 + 2 * p;
        atomicAdd(&g_avg[j],     acc[k].x);
        atomicAdd(&g_avg[j + 1], acc[k].y);
    }

    if (h == 0 && t == 0) {
        float H = 0.f, C = 0.f;
#pragma unroll
        for (int w = 0; w < 16; w++) { H += SWH[w]; C += SWC[w]; }
        g_pH[rg] = H; g_pC[rg] = C;
    }
}

// Finalize: 32 blocks x 512 threads, one code per thread. Reads the 64 KB
// g_avg (L2-hot), computes codebook entropy, zeroes g_avg for the next
// replay, and the last block writes the 4 scalars + resets ticket state.
__global__ __launch_bounds__(NT_F) void lfq_final_kernel(float* __restrict__ out)
{
    const int t = threadIdx.x;
    const int j = blockIdx.x * NT_F + t;

    const float s = g_avg[j];
    g_avg[j] = 0.f;                               // reset for next graph replay
    const float a = s * (1.f / (float)NROW);
    const float term = a * logf(a + 1e-5f);       // a==0 -> 0, matches ref

    __shared__ float red[NT_F];
    __shared__ int last;
    red[t] = term;
    __syncthreads();
#pragma unroll
    for (int off = NT_F / 2; off > 0; off >>= 1) {
        if (t < off) red[t] += red[t + off];
        __syncthreads();
    }
    if (t == 0) {
        const long long v = __double2ll_rn((double)red[0] * FIX_SCALE);
        atomicAdd(&g_accT, (unsigned long long)v);
        __threadfence();
        last = (atomicAdd(&g_ticket, 1u) == NBLK_F - 1) ? 1 : 0;
    }
    __syncthreads();
    if (!last) return;

    // final block: assemble scalars
    __shared__ float fred[64];
    if (t < 64) fred[t] = (t < RG) ? g_pH[t] : 0.f;
    __syncthreads();
#pragma unroll
    for (int off = 32; off > 0; off >>= 1) {
        if (t < off) fred[t] += fred[t + off];
        __syncthreads();
    }
    const float sumH = fred[0];
    __syncthreads();
    if (t < 64) fred[t] = (t < RG) ? g_pC[t] : 0.f;
    __syncthreads();
#pragma unroll
    for (int off = 32; off > 0; off >>= 1) {
        if (t < off) fred[t] += fred[t + off];
        __syncthreads();
    }
    const float sumC = fred[0];

    if (t == 0) {
        const long long tot = (long long)atomicAdd(&g_accT, 0ull);
        const float sumT = (float)((double)tot * (1.0 / FIX_SCALE));
        const float per_sample = sumH * (1.f / (float)NROW);
        const float cb_entropy = -sumT;
        float* sc = out + NROW * NDIM + NROW;
        sc[0] = per_sample;
        sc[1] = cb_entropy;
        sc[2] = per_sample - cb_entropy;
        sc[3] = sumC * (1.f / (float)(NROW * NDIM));
        // reset cross-replay state (g_avg already zeroed element-wise above)
        g_accT = 0ull;
        g_ticket = 0u;
    }
}

extern "C" void kernel_launch(void* const* d_in, const int* in_sizes, int n_in,
                              void* d_out, int out_size)
{
    (void)in_sizes; (void)n_in; (void)out_size;
    const float* x = (const float*)d_in[0];   // [2,2048,14] float32
    float* out = (float*)d_out;

    cudaFuncSetAttribute(lfq_rows_kernel,
                         cudaFuncAttributeMaxDynamicSharedMemorySize, SMEM_BYTES);
    lfq_rows_kernel<<<GRID_A, NT_A, SMEM_BYTES>>>(x, out);
    lfq_final_kernel<<<NBLK_F, NT_F>>>(out);
}